// round 16
// baseline (speedup 1.0000x reference)
#include <cuda_runtime.h>
#include <cuda_bf16.h>
#include <cstdint>
#include <cstddef>

// Shapes (fixed)
#define BW 64
#define BO 64
#define TW 32
#define TO 36
#define DD 512
#define NTILE (BW * BO)

// Swizzled tile layout for w/u: row r (512 floats = 128 float4-words):
// logical word k4 stored at  r*128 + (k4 ^ ((r>>2)&7)).
// Readers iterate LOGICAL k and apply the XOR in the address.
#define SWZW(r, k4) ((((r) * 128) + ((k4) ^ (((r) >> 2) & 7))) * 4)

// dynamic smem layout (float offsets)
#define OFF_U 16384                    // w: 32*512 swizzled
#define OFF_O (OFF_U + 18432)          // u: 36*512 swizzled
#define OFF_PART (OFF_O + 18432)       // o: 36*512 linear
#define SMEM_FLOATS (OFF_PART + 4608)  // part: 4*1152 (K-groups 1..4)
#define SMEM_BYTES (SMEM_FLOATS * 4)   // 231,424 B <= 232,448

// scratch
__device__ float g_logits[BW * TW * BO];  // [w][t][b]
__device__ float g_wloss[BW];

__device__ __forceinline__ void cpa16(float* s, const float* g) {
    uint32_t sa = (uint32_t)__cvta_generic_to_shared(s);
    asm volatile("cp.async.cg.shared.global [%0], [%1], 16;" :: "r"(sa), "l"(g));
}
__device__ __forceinline__ void cp_commit() { asm volatile("cp.async.commit_group;"); }
__device__ __forceinline__ void cp_wait0()  { asm volatile("cp.async.wait_group 0;"); }
__device__ __forceinline__ void cp_wait1()  { asm volatile("cp.async.wait_group 1;"); }

// ---- packed fp32x2 helpers (Blackwell dual-fp32 FMA) ----
__device__ __forceinline__ void fma2(unsigned long long& d,
                                     unsigned long long a, unsigned long long b) {
    asm("fma.rn.f32x2 %0, %1, %2, %0;" : "+l"(d) : "l"(a), "l"(b));
}
__device__ __forceinline__ unsigned long long packf2(float lo, float hi) {
    unsigned long long v;
    asm("mov.b64 %0, {%1, %2};" : "=l"(v) : "r"(__float_as_uint(lo)), "r"(__float_as_uint(hi)));
    return v;
}
__device__ __forceinline__ void unpackf2(unsigned long long v, float& lo, float& hi) {
    unsigned a, b;
    asm("mov.b64 {%0, %1}, %2;" : "=r"(a), "=r"(b) : "l"(v));
    lo = __uint_as_float(a); hi = __uint_as_float(b);
}
__device__ __forceinline__ float f2sum(unsigned long long v) {
    float lo, hi; unpackf2(v, lo, hi); return lo + hi;
}

__global__ void __launch_bounds__(512, 1)
cap_main(const float* __restrict__ o_g, const float* __restrict__ u_g,
         const float* __restrict__ w_g,
         float* __restrict__ att_out, float* __restrict__ avo_out)
{
    extern __shared__ float sm[];
    float* w_s    = sm;                 // [32][512] swizzled
    float* u_s    = sm + OFF_U;         // [36][512] swizzled
    float* o_s    = sm + OFF_O;         // [36][512] linear
    float* part   = sm + OFF_PART;      // [4][36][32] k-split partials (groups 1..4)
    float* att_ts = part;               // [36][36] overlays part
    float* lp     = part + 1296;        // [32 t][4] logits partials

    const int tid  = threadIdx.x;
    const int lane = tid & 31;
    const int warp = tid >> 5;

    // tile range (wb-major -> w reuse)
    const int nblk  = gridDim.x;
    const int r     = blockIdx.x;
    const int bas   = NTILE / nblk, rem = NTILE % nblk;
    const int cnt   = bas + (r < rem ? 1 : 0);
    const int start = r * bas + (r < rem ? r : rem);

    // ---- prologue: load w(wb0) and u(b0), swizzled ----
    {
        const int tile0 = start;
        const int wb0 = tile0 >> 6, b0 = tile0 & 63;
        const float* wg = w_g + (size_t)wb0 * TW * DD;
        const float* ug = u_g + (size_t)b0 * TO * DD;
        for (int i = tid; i < TW * 128; i += 512) {
            int t = i >> 7, k4 = i & 127;
            cpa16(&w_s[SWZW(t, k4)], wg + t * DD + k4 * 4);
        }
        for (int i = tid; i < TO * 128; i += 512) {
            int t = i >> 7, k4 = i & 127;
            cpa16(&u_s[SWZW(t, k4)], ug + t * DD + k4 * 4);
        }
        cp_commit(); cp_wait0(); __syncthreads();
    }

    for (int it = 0; it < cnt; ++it) {
        const int tile = start + it;
        const int wb = tile >> 6, b = tile & 63;

        if (it) { cp_wait0(); __syncthreads(); }   // u (+w) prefetch landed

        // ---- (A) prefetch o(b) into o_s, linear (overlaps stage 1) ----
        {
            const float* og = o_g + (size_t)b * TO * DD;
            for (int i = tid; i < TO * 128; i += 512) {
                int t = i >> 7, k4 = i & 127;
                cpa16(&o_s[t * DD + k4 * 4], og + t * DD + k4 * 4);
            }
            cp_commit();                            // group O
        }

        // ---- stage 1: scores(32x36) = w . u^T, 5-way K-split, 4x4 tiles ----
        // 360 threads (warps 0..10 + 8): better SMSP balance than 288.
        // K chunks (float4 words): 26,26,26,25,25. XOR swizzle applied to the
        // full logical word index (chunk bounds are not 8-aligned).
        float s1acc[4][4];
        int t0a = 0, o0a = 0;
        if (tid < 360) {
            const int g    = tid / 72;
            const int id72 = tid % 72;
            const int oc   = id72 >> 3;      // 0..8
            const int tr   = id72 & 7;       // 0..7
            t0a = tr * 4; o0a = oc * 4;
            const int axor = tr;
            const int bxor = oc & 7;
            const int gstart = 26 * g - ((g > 3) ? (g - 3) : 0);
            const int glen   = (g < 3) ? 26 : 25;

            const float* baseA[4];
            const float* baseB[4];
            #pragma unroll
            for (int i = 0; i < 4; i++) baseA[i] = w_s + (t0a + i) * 512;
            #pragma unroll
            for (int j = 0; j < 4; j++) baseB[j] = u_s + (o0a + j) * 512;

            unsigned long long accp[4][4];
            #pragma unroll
            for (int i = 0; i < 4; i++)
                #pragma unroll
                for (int j = 0; j < 4; j++) accp[i][j] = 0ull;

            #pragma unroll 2
            for (int kk = 0; kk < glen; kk++) {
                const int K = gstart + kk;
                const int offA = ((K ^ axor) << 2);
                const int offB = ((K ^ bxor) << 2);
                ulonglong2 aq[4], bq[4];
                #pragma unroll
                for (int i = 0; i < 4; i++) aq[i] = *(const ulonglong2*)(baseA[i] + offA);
                #pragma unroll
                for (int j = 0; j < 4; j++) bq[j] = *(const ulonglong2*)(baseB[j] + offB);
                #pragma unroll
                for (int i = 0; i < 4; i++) {
                    #pragma unroll
                    for (int j = 0; j < 4; j++) {
                        fma2(accp[i][j], aq[i].x, bq[j].x);
                        fma2(accp[i][j], aq[i].y, bq[j].y);
                    }
                }
            }
            #pragma unroll
            for (int i = 0; i < 4; i++)
                #pragma unroll
                for (int j = 0; j < 4; j++)
                    s1acc[i][j] = f2sum(accp[i][j]);

            if (g) {  // groups 1..4 spill partials; group 0 keeps registers
                float* pg = part + (g - 1) * 1152;
                #pragma unroll
                for (int i = 0; i < 4; i++)
                    #pragma unroll
                    for (int j = 0; j < 4; j++)
                        pg[(o0a + j) * 32 + (t0a + i)] = s1acc[i][j];
            }
        }
        __syncthreads();

        // ---- (D) prefetch u(next) into u_s (swizzled) ----
        {
            const int ntile = (it + 1 < cnt) ? tile + 1 : tile;
            const int nb = ntile & 63;
            const float* ug = u_g + (size_t)nb * TO * DD;
            for (int i = tid; i < TO * 128; i += 512) {
                int t = i >> 7, k4 = i & 127;
                cpa16(&u_s[SWZW(t, k4)], ug + t * DD + k4 * 4);
            }
            cp_commit();                            // group U
        }

        // ---- reduce K-split partials into group-0 registers, scale ----
        const float scale = 0.044194173824159216f;  // 1/sqrt(512)
        if (tid < 72) {
            #pragma unroll
            for (int i = 0; i < 4; i++)
                #pragma unroll
                for (int j = 0; j < 4; j++) {
                    const int idx = (o0a + j) * 32 + (t0a + i);
                    s1acc[i][j] = (s1acc[i][j] + part[idx] + part[1152 + idx]
                                   + part[2304 + idx] + part[3456 + idx]) * scale;
                }
        }
        __syncthreads();
        if (tid < 72) {
            #pragma unroll
            for (int i = 0; i < 4; i++)
                #pragma unroll
                for (int j = 0; j < 4; j++)
                    att_ts[(o0a + j) * 36 + (t0a + i)] = s1acc[i][j];
        }
        __syncthreads();

        // ---- softmax over To; warp handles t = warp and warp+16 ----
        #pragma unroll
        for (int rr = 0; rr < 2; rr++) {
            const int t = warp + rr * 16;
            float v0 = att_ts[lane * 36 + t];
            float v1 = (lane < 4) ? att_ts[(32 + lane) * 36 + t] : -3.4e38f;
            float mx = fmaxf(v0, v1);
            #pragma unroll
            for (int off = 16; off; off >>= 1) mx = fmaxf(mx, __shfl_xor_sync(0xffffffffu, mx, off));
            float e0 = __expf(v0 - mx);
            float e1 = (lane < 4) ? __expf(v1 - mx) : 0.f;
            float s = e0 + e1;
            #pragma unroll
            for (int off = 16; off; off >>= 1) s += __shfl_xor_sync(0xffffffffu, s, off);
            float rs = __frcp_rn(s);
            float p0 = e0 * rs;
            att_ts[lane * 36 + t] = p0;
            float* ao = att_out + ((size_t)((wb * BO + b) * TW + t)) * TO;
            ao[lane] = p0;
            if (lane < 4) {
                float p1 = e1 * rs;
                att_ts[(32 + lane) * 36 + t] = p1;
                ao[32 + lane] = p1;
            }
        }
        cp_wait1();                                 // group O done (U may still fly)
        __syncthreads();

        // ---- stage 2: att_V_o = att(32x36).o(36x512), 8t x 4d tiles ----
        // 4 groups (tg) x 128 c-lanes. att reads are warp-uniform broadcasts
        // (2 LDS.128 serve 8 t's); o reads are 4 dense LDS.32 per o.
        const int tg = tid >> 7;       // 0..3
        const int c  = tid & 127;      // 0..127
        const int t0 = tg * 8;
        unsigned long long accp2[8][2];
        #pragma unroll
        for (int i = 0; i < 8; i++) { accp2[i][0] = 0ull; accp2[i][1] = 0ull; }

        #pragma unroll 2
        for (int o = 0; o < 36; o++) {
            float4 a1 = *(const float4*)&att_ts[o * 36 + t0];      // warp-uniform
            float4 a2 = *(const float4*)&att_ts[o * 36 + t0 + 4];  // warp-uniform
            unsigned long long avp[8] = {
                packf2(a1.x, a1.x), packf2(a1.y, a1.y), packf2(a1.z, a1.z), packf2(a1.w, a1.w),
                packf2(a2.x, a2.x), packf2(a2.y, a2.y), packf2(a2.z, a2.z), packf2(a2.w, a2.w)
            };
            unsigned long long ov0 = packf2(o_s[o * DD + c],       o_s[o * DD + c + 128]);
            unsigned long long ov1 = packf2(o_s[o * DD + c + 256], o_s[o * DD + c + 384]);
            #pragma unroll
            for (int i = 0; i < 8; i++) {
                fma2(accp2[i][0], avp[i], ov0);
                fma2(accp2[i][1], avp[i], ov1);
            }
        }

        // dense scalar STG stores + swizzle-aware w reads for fused logits
        float* avo = avo_out + ((size_t)((wb * BO + b) * TW + t0)) * DD;
        #pragma unroll
        for (int i = 0; i < 8; i++) {
            float v0, v1, v2, v3;
            unpackf2(accp2[i][0], v0, v1);
            unpackf2(accp2[i][1], v2, v3);
            float* row = avo + (size_t)i * DD;
            row[c]       = v0;
            row[c + 128] = v1;
            row[c + 256] = v2;
            row[c + 384] = v3;

            const int xorv = ((t0 + i) >> 2) & 7;
            const int cb = (((c >> 2) ^ xorv) << 2) + (c & 3);
            const float* wr = w_s + (t0 + i) * 512 + cb;
            float l = v0 * wr[0] + v1 * wr[128] + v2 * wr[256] + v3 * wr[384];
            #pragma unroll
            for (int off = 16; off; off >>= 1) l += __shfl_xor_sync(0xffffffffu, l, off);
            if (lane == 0) lp[(t0 + i) * 4 + (warp & 3)] = l;
        }
        __syncthreads();
        if (tid < 32)
            g_logits[((size_t)wb * TW + tid) * BO + b] =
                lp[tid * 4] + lp[tid * 4 + 1] + lp[tid * 4 + 2] + lp[tid * 4 + 3];

        // ---- (H) prefetch w if wb changes ----
        if (it + 1 < cnt) {
            const int nwb = (tile + 1) >> 6;
            if (nwb != wb) {
                const float* wg = w_g + (size_t)nwb * TW * DD;
                for (int i = tid; i < TW * 128; i += 512) {
                    int t = i >> 7, k4 = i & 127;
                    cpa16(&w_s[SWZW(t, k4)], wg + t * DD + k4 * 4);
                }
                cp_commit();                        // group W
            }
        }
    }
    cp_wait0();
}

// ---- loss, stage 1: per-w masked mean of (diag - lse) ----
__global__ void cap_loss1(const int* __restrict__ mask)
{
    __shared__ float sacc[8], scnt[8];
    const int w = blockIdx.x;
    const int tid = threadIdx.x, warp = tid >> 5, lane = tid & 31;
    const float* lw = g_logits + (size_t)w * TW * BO;
    float acc = 0.f, cntv = 0.f;
    for (int t = warp; t < TW; t += 8) {
        float v0 = lw[t * BO + lane];
        float v1 = lw[t * BO + 32 + lane];
        float mx = fmaxf(v0, v1);
        #pragma unroll
        for (int off = 16; off; off >>= 1) mx = fmaxf(mx, __shfl_xor_sync(0xffffffffu, mx, off));
        float s = expf(v0 - mx) + expf(v1 - mx);
        #pragma unroll
        for (int off = 16; off; off >>= 1) s += __shfl_xor_sync(0xffffffffu, s, off);
        if (lane == 0 && mask[w * TW + t] == 0) {
            acc += lw[t * BO + w] - (mx + logf(s));
            cntv += 1.f;
        }
    }
    if (lane == 0) { sacc[warp] = acc; scnt[warp] = cntv; }
    __syncthreads();
    if (tid == 0) {
        float a = 0.f, c = 0.f;
        #pragma unroll
        for (int i = 0; i < 8; i++) { a += sacc[i]; c += scnt[i]; }
        g_wloss[w] = a / (c + 1e-6f);
    }
}

// ---- loss, stage 2: -mean over w ----
__global__ void cap_loss2(float* __restrict__ out)
{
    __shared__ float sh[2];
    const int tid = threadIdx.x, lane = tid & 31, warp = tid >> 5;
    float v = g_wloss[tid];
    #pragma unroll
    for (int off = 16; off; off >>= 1) v += __shfl_xor_sync(0xffffffffu, v, off);
    if (lane == 0) sh[warp] = v;
    __syncthreads();
    if (tid == 0) out[0] = -(sh[0] + sh[1]) * (1.0f / 64.0f);
}

extern "C" void kernel_launch(void* const* d_in, const int* in_sizes, int n_in,
                              void* d_out, int out_size)
{
    (void)in_sizes; (void)n_in; (void)out_size;
    const float* o_g  = (const float*)d_in[0];
    const float* u_g  = (const float*)d_in[1];
    const float* w_g  = (const float*)d_in[2];
    const int*   mask = (const int*)d_in[3];
    float* out = (float*)d_out;

    static int nsm = 0;
    if (nsm == 0) {
        int dev = 0;
        cudaGetDevice(&dev);
        cudaDeviceGetAttribute(&nsm, cudaDevAttrMultiProcessorCount, dev);
        if (nsm <= 0) nsm = 148;
        cudaFuncSetAttribute(cap_main, cudaFuncAttributeMaxDynamicSharedMemorySize, SMEM_BYTES);
    }

    // output layout: [0]=loss, att (Bw,Bo,Tw,To), att_V_o (Bw,Bo,Tw,D)
    float* att_out = out + 1;
    float* avo_out = out + 1 + (size_t)BW * BO * TW * TO;

    cap_main<<<nsm, 512, SMEM_BYTES>>>(o_g, u_g, w_g, att_out, avo_out);
    cap_loss1<<<64, 256>>>(mask);
    cap_loss2<<<1, 64>>>(out);
}